// round 1
// baseline (speedup 1.0000x reference)
#include <cuda_runtime.h>
#include <math.h>

#define NNODES 262144
#define KNBR 8

// Scratch (allocation-free): intermediates + precomputed inverse distances.
__device__ float g_h1[(size_t)NNODES * 128];
__device__ float g_h2[(size_t)NNODES * 128];
__device__ float g_invd[(size_t)NNODES * KNBR];

// ---------------------------------------------------------------------------
// invdist: d = ||pos[n] - pos[nbr[n,k]]||; invd = (d==0) ? 1/0.5 : 1/d
// Matches reference: where(dist==0, 0.5, dist); msgs / dist.
// ---------------------------------------------------------------------------
__global__ void invdist_kernel(const float* __restrict__ pos,
                               const int* __restrict__ nbr) {
    int i = blockIdx.x * blockDim.x + threadIdx.x;
    if (i >= NNODES * KNBR) return;
    int n = i >> 3;
    int j = nbr[i];
    float dx = pos[3 * n + 0] - pos[3 * j + 0];
    float dy = pos[3 * n + 1] - pos[3 * j + 1];
    float dz = pos[3 * n + 2] - pos[3 * j + 2];
    float d = sqrtf(dx * dx + dy * dy + dz * dz);
    g_invd[i] = (d == 0.0f) ? 2.0f : 1.0f / d;
}

// ---------------------------------------------------------------------------
// Gathered GEMM layer:
//   out[n, :] = concat_k( hin[nbr[n,k], :] * invd[n,k] ) @ W + b  (opt LeakyReLU)
//
// Block tile: TM nodes x FOUT cols. Inner dim K*FIN processed in chunks of 128.
// Per chunk: gather X tile [TM,128] into smem, stage W chunk [128,FOUT] in smem.
// Thread tile: TTM nodes x 4 cols; float4 smem traffic so the block is
// FMA-pipe bound rather than LDS-phase bound.
// ---------------------------------------------------------------------------
template <int FIN, int FOUT, int TM, int TTM, int THREADS, bool RELU>
__global__ void __launch_bounds__(THREADS, 2)
layer_kernel(const float* __restrict__ hin, const int* __restrict__ nbr,
             const float* __restrict__ Wg, const float* __restrict__ bg,
             float* __restrict__ out) {
    constexpr int CPT = FOUT / 4;              // float4 col groups
    constexpr int NCHUNK = (KNBR * FIN) / 128; // 128-wide inner chunks

    extern __shared__ float smem[];
    float* Xs = smem;                           // TM * 128
    float* Ws = Xs + TM * 128;                  // 128 * FOUT
    int*   sN = (int*)(Ws + 128 * FOUT);        // TM * KNBR
    float* sD = (float*)(sN + TM * KNBR);       // TM * KNBR

    const int tid = threadIdx.x;
    const int tx = tid % CPT;
    const int ty = tid / CPT;
    const int n0 = blockIdx.x * TM;

    for (int idx = tid; idx < TM * KNBR; idx += THREADS) {
        sN[idx] = nbr[n0 * KNBR + idx];
        sD[idx] = g_invd[(size_t)n0 * KNBR + idx];
    }

    float acc[TTM][4];
#pragma unroll
    for (int mm = 0; mm < TTM; mm++) {
        acc[mm][0] = 0.f; acc[mm][1] = 0.f; acc[mm][2] = 0.f; acc[mm][3] = 0.f;
    }

    __syncthreads();

    for (int chunk = 0; chunk < NCHUNK; chunk++) {
        // --- gather scaled X tile (coalesced: one warp covers one 512B row) ---
        for (int idx = tid; idx < TM * 32; idx += THREADS) {
            int row = idx >> 5;
            int f4  = idx & 31;
            int j   = chunk * 128 + f4 * 4;   // global inner index
            int k   = j / FIN;
            int f   = j % FIN;
            const float4 v = *reinterpret_cast<const float4*>(
                hin + (size_t)sN[row * KNBR + k] * FIN + f);
            float s = sD[row * KNBR + k];
            float4 r;
            r.x = v.x * s; r.y = v.y * s; r.z = v.z * s; r.w = v.w * s;
            *reinterpret_cast<float4*>(Xs + row * 128 + f4 * 4) = r;
        }
        // --- stage W chunk ---
        {
            const float4* W4 =
                reinterpret_cast<const float4*>(Wg) + (size_t)chunk * 128 * CPT;
            float4* Ws4 = reinterpret_cast<float4*>(Ws);
            for (int idx = tid; idx < 128 * CPT; idx += THREADS) Ws4[idx] = W4[idx];
        }
        __syncthreads();

        const float4* Xs4 = reinterpret_cast<const float4*>(Xs);
        const float4* Ws4 = reinterpret_cast<const float4*>(Ws);
#pragma unroll 4
        for (int i4 = 0; i4 < 32; i4++) {
            float xv[TTM][4];
#pragma unroll
            for (int mm = 0; mm < TTM; mm++) {
                float4 t = Xs4[(ty * TTM + mm) * 32 + i4];
                xv[mm][0] = t.x; xv[mm][1] = t.y; xv[mm][2] = t.z; xv[mm][3] = t.w;
            }
#pragma unroll
            for (int sub = 0; sub < 4; sub++) {
                float4 w = Ws4[(i4 * 4 + sub) * CPT + tx];
#pragma unroll
                for (int mm = 0; mm < TTM; mm++) {
                    acc[mm][0] += xv[mm][sub] * w.x;
                    acc[mm][1] += xv[mm][sub] * w.y;
                    acc[mm][2] += xv[mm][sub] * w.z;
                    acc[mm][3] += xv[mm][sub] * w.w;
                }
            }
        }
        __syncthreads();
    }

    // --- epilogue: bias (+ optional LeakyReLU), coalesced float4 stores ---
    float4 bv = reinterpret_cast<const float4*>(bg)[tx];
#pragma unroll
    for (int mm = 0; mm < TTM; mm++) {
        float4 o;
        o.x = acc[mm][0] + bv.x;
        o.y = acc[mm][1] + bv.y;
        o.z = acc[mm][2] + bv.z;
        o.w = acc[mm][3] + bv.w;
        if (RELU) {
            o.x = (o.x >= 0.f) ? o.x : 0.01f * o.x;
            o.y = (o.y >= 0.f) ? o.y : 0.01f * o.y;
            o.z = (o.z >= 0.f) ? o.z : 0.01f * o.z;
            o.w = (o.w >= 0.f) ? o.w : 0.01f * o.w;
        }
        *reinterpret_cast<float4*>(
            out + (size_t)(n0 + ty * TTM + mm) * FOUT + tx * 4) = o;
    }
}

// Instantiations
// layer0: FIN=16  -> FOUT=128, TM=64,  TTM=8, 256 thr
// layer1: FIN=128 -> FOUT=128, TM=64,  TTM=8, 256 thr, LeakyReLU
// layer2: FIN=128 -> FOUT=16,  TM=128, TTM=4, 128 thr
static constexpr size_t SMEM_L01 = (64 * 128 + 128 * 128) * 4 + 64 * KNBR * 8;   // 102400
static constexpr size_t SMEM_L2  = (128 * 128 + 128 * 16) * 4 + 128 * KNBR * 8;  // 81920

extern "C" void kernel_launch(void* const* d_in, const int* in_sizes, int n_in,
                              void* d_out, int out_size) {
    const float* h   = (const float*)d_in[0];
    const float* pos = (const float*)d_in[1];
    const int*   nbr = (const int*)d_in[2];
    const float* W0  = (const float*)d_in[3];
    const float* b0  = (const float*)d_in[4];
    const float* W1  = (const float*)d_in[5];
    const float* b1  = (const float*)d_in[6];
    const float* W2  = (const float*)d_in[7];
    const float* b2  = (const float*)d_in[8];
    float* out = (float*)d_out;

    float *h1, *h2;
    cudaGetSymbolAddress((void**)&h1, g_h1);
    cudaGetSymbolAddress((void**)&h2, g_h2);

    cudaFuncSetAttribute(
        (const void*)layer_kernel<16, 128, 64, 8, 256, false>,
        cudaFuncAttributeMaxDynamicSharedMemorySize, (int)SMEM_L01);
    cudaFuncSetAttribute(
        (const void*)layer_kernel<128, 128, 64, 8, 256, true>,
        cudaFuncAttributeMaxDynamicSharedMemorySize, (int)SMEM_L01);
    cudaFuncSetAttribute(
        (const void*)layer_kernel<128, 16, 128, 4, 128, false>,
        cudaFuncAttributeMaxDynamicSharedMemorySize, (int)SMEM_L2);

    invdist_kernel<<<(NNODES * KNBR + 255) / 256, 256>>>(pos, nbr);

    layer_kernel<16, 128, 64, 8, 256, false>
        <<<NNODES / 64, 256, SMEM_L01>>>(h, nbr, W0, b0, h1);

    layer_kernel<128, 128, 64, 8, 256, true>
        <<<NNODES / 64, 256, SMEM_L01>>>(h1, nbr, W1, b1, h2);

    layer_kernel<128, 16, 128, 4, 128, false>
        <<<NNODES / 128, 128, SMEM_L2>>>(h2, nbr, W2, b2, out);
}

// round 3
// speedup vs baseline: 2.9017x; 2.9017x over previous
#include <cuda_runtime.h>
#include <cuda_bf16.h>
#include <cstdint>
#include <math.h>

#define NNODES 262144
#define KNBR 8

// ---------------- global scratch (allocation-free) ----------------
__device__ float g_h1[(size_t)NNODES * 128];
__device__ float g_h2[(size_t)NNODES * 128];
__device__ float g_invd[(size_t)NNODES * KNBR];
// W transposed to [N, K] K-major, split into bf16 hi/lo
__device__ __nv_bfloat16 g_wt0h[128 * 128],  g_wt0l[128 * 128];
__device__ __nv_bfloat16 g_wt1h[128 * 1024], g_wt1l[128 * 1024];
__device__ __nv_bfloat16 g_wt2h[16 * 1024],  g_wt2l[16 * 1024];

// ---------------- helpers ----------------
__device__ __forceinline__ uint32_t smem_u32(const void* p) {
    uint32_t a;
    asm("{ .reg .u64 t; cvta.to.shared.u64 t, %1; cvt.u32.u64 %0, t; }"
        : "=r"(a) : "l"(p));
    return a;
}
__device__ __forceinline__ uint32_t swz128(uint32_t off) {
    return off ^ ((off >> 3) & 0x70);
}
__device__ __forceinline__ void ldsm4(uint32_t* r, uint32_t addr) {
    asm volatile("ldmatrix.sync.aligned.m8n8.x4.shared.b16 {%0,%1,%2,%3}, [%4];"
                 : "=r"(r[0]), "=r"(r[1]), "=r"(r[2]), "=r"(r[3]) : "r"(addr));
}
__device__ __forceinline__ void mma16816(float* d, const uint32_t* a,
                                         uint32_t b0, uint32_t b1) {
    asm volatile(
        "mma.sync.aligned.m16n8k16.row.col.f32.bf16.bf16.f32 "
        "{%0,%1,%2,%3}, {%4,%5,%6,%7}, {%8,%9}, {%0,%1,%2,%3};"
        : "+f"(d[0]), "+f"(d[1]), "+f"(d[2]), "+f"(d[3])
        : "r"(a[0]), "r"(a[1]), "r"(a[2]), "r"(a[3]), "r"(b0), "r"(b1));
}

// ---------------- small prep kernels ----------------
__global__ void invdist_kernel(const float* __restrict__ pos,
                               const int* __restrict__ nbr) {
    int i = blockIdx.x * blockDim.x + threadIdx.x;
    if (i >= NNODES * KNBR) return;
    int n = i >> 3;
    int j = nbr[i];
    float dx = pos[3 * n + 0] - pos[3 * j + 0];
    float dy = pos[3 * n + 1] - pos[3 * j + 1];
    float dz = pos[3 * n + 2] - pos[3 * j + 2];
    float d = sqrtf(dx * dx + dy * dy + dz * dz);
    g_invd[i] = (d == 0.0f) ? 2.0f : 1.0f / d;
}

// W [K, N] fp32 -> Wt [N, K] bf16 hi/lo
__global__ void wprep_kernel(const float* __restrict__ W, int K, int N,
                             __nv_bfloat16* __restrict__ wh,
                             __nv_bfloat16* __restrict__ wl) {
    int i = blockIdx.x * blockDim.x + threadIdx.x;
    if (i >= K * N) return;
    int k = i / N, n = i % N;
    float w = W[i];
    __nv_bfloat16 h = __float2bfloat16(w);
    float lo = w - __bfloat162float(h);
    wh[n * K + k] = h;
    wl[n * K + k] = __float2bfloat16(lo);
}

// ---------------- gathered GEMM layer via mma.sync (bf16 split x3) ---------
// out[128-tile, FOUT] = (gather_scaled(hin)[128, KTOT]) @ Wt^T + b
template <int FIN, int FOUT, int KTOT, bool RELU>
struct Cfg {
    static constexpr int TM = 128;
    static constexpr int KC = 64;                 // k per chunk (128B bf16 rows)
    static constexpr int NCH = KTOT / KC;
    static constexpr int OFF_SN = 0;              // int  [128*8]
    static constexpr int OFF_SD = 4096;           // f32  [128*8]
    static constexpr int OFF_AH = 8192;           // bf16 [128][64] swizzled
    static constexpr int OFF_AL = OFF_AH + 128 * 128;
    static constexpr int OFF_BH = OFF_AL + 128 * 128;  // bf16 [FOUT][64]
    static constexpr int OFF_BL = OFF_BH + FOUT * 128;
    static constexpr int SMEM_BYTES = OFF_BL + FOUT * 128;
};

template <int FIN, int FOUT, int KTOT, bool RELU>
__global__ void __launch_bounds__(256, 2)
layer_kernel(const float* __restrict__ hin, const int* __restrict__ nbr,
             const __nv_bfloat16* __restrict__ wh,
             const __nv_bfloat16* __restrict__ wl,
             const float* __restrict__ bg, float* __restrict__ out) {
    using C = Cfg<FIN, FOUT, KTOT, RELU>;
    extern __shared__ char smem[];
    const uint32_t sbase = smem_u32(smem);
    const int tid = threadIdx.x;
    const int wid = tid >> 5;
    const int lane = tid & 31;
    const int n0 = blockIdx.x * C::TM;

    int* sN = (int*)(smem + C::OFF_SN);
    float* sD = (float*)(smem + C::OFF_SD);
    for (int idx = tid; idx < C::TM * KNBR; idx += 256) {
        sN[idx] = nbr[n0 * KNBR + idx];
        sD[idx] = g_invd[(size_t)n0 * KNBR + idx];
    }

    float acc[FOUT / 8][4];
#pragma unroll
    for (int t = 0; t < FOUT / 8; t++) {
        acc[t][0] = 0.f; acc[t][1] = 0.f; acc[t][2] = 0.f; acc[t][3] = 0.f;
    }
    __syncthreads();

    // precomputed per-lane ldmatrix offset pieces
    const int mat = lane >> 3, r = lane & 7;
    const int mrow = wid * 16;

    for (int ch = 0; ch < C::NCH; ch++) {
        // ---- gather + scale + bf16 hi/lo split of A tile [128, 64] ----
        for (int idx = tid; idx < C::TM * 16; idx += 256) {
            int row = idx >> 4, q = idx & 15;
            int j = ch * C::KC + q * 4;
            int k = j / FIN, f = j % FIN;
            const float4 v = *reinterpret_cast<const float4*>(
                hin + (size_t)sN[row * KNBR + k] * FIN + f);
            float s = sD[row * KNBR + k];
            float x0 = v.x * s, x1 = v.y * s, x2 = v.z * s, x3 = v.w * s;
            __nv_bfloat16 h0 = __float2bfloat16(x0), h1 = __float2bfloat16(x1);
            __nv_bfloat16 h2 = __float2bfloat16(x2), h3 = __float2bfloat16(x3);
            __nv_bfloat16 l0 = __float2bfloat16(x0 - __bfloat162float(h0));
            __nv_bfloat16 l1 = __float2bfloat16(x1 - __bfloat162float(h1));
            __nv_bfloat16 l2 = __float2bfloat16(x2 - __bfloat162float(h2));
            __nv_bfloat16 l3 = __float2bfloat16(x3 - __bfloat162float(h3));
            uint2 ph, pl;
            ph.x = (uint32_t)__bfloat16_as_ushort(h0) |
                   ((uint32_t)__bfloat16_as_ushort(h1) << 16);
            ph.y = (uint32_t)__bfloat16_as_ushort(h2) |
                   ((uint32_t)__bfloat16_as_ushort(h3) << 16);
            pl.x = (uint32_t)__bfloat16_as_ushort(l0) |
                   ((uint32_t)__bfloat16_as_ushort(l1) << 16);
            pl.y = (uint32_t)__bfloat16_as_ushort(l2) |
                   ((uint32_t)__bfloat16_as_ushort(l3) << 16);
            uint32_t off = swz128((uint32_t)(row * 128 + q * 8));
            *reinterpret_cast<uint2*>(smem + C::OFF_AH + off) = ph;
            *reinterpret_cast<uint2*>(smem + C::OFF_AL + off) = pl;
        }
        // ---- stage W tile [FOUT, 64] hi/lo ----
        for (int idx = tid; idx < FOUT * 16; idx += 256) {
            int row = idx >> 4, q = idx & 15;
            size_t g = (size_t)row * KTOT + ch * C::KC + q * 4;
            uint2 vh = *reinterpret_cast<const uint2*>(wh + g);
            uint2 vl = *reinterpret_cast<const uint2*>(wl + g);
            uint32_t off = swz128((uint32_t)(row * 128 + q * 8));
            *reinterpret_cast<uint2*>(smem + C::OFF_BH + off) = vh;
            *reinterpret_cast<uint2*>(smem + C::OFF_BL + off) = vl;
        }
        __syncthreads();

#pragma unroll
        for (int ks = 0; ks < C::KC / 16; ks++) {
            // A fragments (hi, lo): 16x16 tile at (mrow, ks*16)
            int arow = mrow + ((mat & 1) << 3) + r;
            int acol = (ks << 4) + ((mat >> 1) << 3);
            uint32_t abyte = swz128((uint32_t)(arow * 128 + acol * 2));
            uint32_t ah[4], al[4];
            ldsm4(ah, sbase + C::OFF_AH + abyte);
            ldsm4(al, sbase + C::OFF_AL + abyte);
#pragma unroll
            for (int nt2 = 0; nt2 < FOUT / 16; nt2++) {
                int brow = nt2 * 16 + ((mat >> 1) << 3) + r;
                int bcol = (ks << 4) + ((mat & 1) << 3);
                uint32_t bbyte = swz128((uint32_t)(brow * 128 + bcol * 2));
                uint32_t bh[4], bl[4];
                ldsm4(bh, sbase + C::OFF_BH + bbyte);
                ldsm4(bl, sbase + C::OFF_BL + bbyte);
                float* d0 = acc[nt2 * 2];
                float* d1 = acc[nt2 * 2 + 1];
                mma16816(d0, ah, bh[0], bh[1]);
                mma16816(d0, ah, bl[0], bl[1]);
                mma16816(d0, al, bh[0], bh[1]);
                mma16816(d1, ah, bh[2], bh[3]);
                mma16816(d1, ah, bl[2], bl[3]);
                mma16816(d1, al, bh[2], bh[3]);
            }
        }
        __syncthreads();
    }

    // ---- epilogue: bias (+LeakyReLU), float2 stores ----
    const int g = lane >> 2, tig = lane & 3;
    const int row0 = n0 + mrow + g;
#pragma unroll
    for (int nt = 0; nt < FOUT / 8; nt++) {
        int col = nt * 8 + tig * 2;
        float b0 = bg[col], b1 = bg[col + 1];
        float v00 = acc[nt][0] + b0, v01 = acc[nt][1] + b1;
        float v10 = acc[nt][2] + b0, v11 = acc[nt][3] + b1;
        if (RELU) {
            v00 = (v00 >= 0.f) ? v00 : 0.01f * v00;
            v01 = (v01 >= 0.f) ? v01 : 0.01f * v01;
            v10 = (v10 >= 0.f) ? v10 : 0.01f * v10;
            v11 = (v11 >= 0.f) ? v11 : 0.01f * v11;
        }
        *reinterpret_cast<float2*>(out + (size_t)row0 * FOUT + col) =
            make_float2(v00, v01);
        *reinterpret_cast<float2*>(out + (size_t)(row0 + 8) * FOUT + col) =
            make_float2(v10, v11);
    }
}

// ---------------- host launch ----------------
extern "C" void kernel_launch(void* const* d_in, const int* in_sizes, int n_in,
                              void* d_out, int out_size) {
    const float* h   = (const float*)d_in[0];
    const float* pos = (const float*)d_in[1];
    const int*   nbr = (const int*)d_in[2];
    const float* W0  = (const float*)d_in[3];
    const float* b0  = (const float*)d_in[4];
    const float* W1  = (const float*)d_in[5];
    const float* b1  = (const float*)d_in[6];
    const float* W2  = (const float*)d_in[7];
    const float* b2  = (const float*)d_in[8];
    float* out = (float*)d_out;

    float *h1, *h2;
    cudaGetSymbolAddress((void**)&h1, g_h1);
    cudaGetSymbolAddress((void**)&h2, g_h2);
    __nv_bfloat16 *wt0h, *wt0l, *wt1h, *wt1l, *wt2h, *wt2l;
    cudaGetSymbolAddress((void**)&wt0h, g_wt0h);
    cudaGetSymbolAddress((void**)&wt0l, g_wt0l);
    cudaGetSymbolAddress((void**)&wt1h, g_wt1h);
    cudaGetSymbolAddress((void**)&wt1l, g_wt1l);
    cudaGetSymbolAddress((void**)&wt2h, g_wt2h);
    cudaGetSymbolAddress((void**)&wt2l, g_wt2l);

    constexpr int SM0 = Cfg<16, 128, 128, false>::SMEM_BYTES;
    constexpr int SM1 = Cfg<128, 128, 1024, true>::SMEM_BYTES;
    constexpr int SM2 = Cfg<128, 16, 1024, false>::SMEM_BYTES;

    cudaFuncSetAttribute((const void*)layer_kernel<16, 128, 128, false>,
                         cudaFuncAttributeMaxDynamicSharedMemorySize, SM0);
    cudaFuncSetAttribute((const void*)layer_kernel<128, 128, 1024, true>,
                         cudaFuncAttributeMaxDynamicSharedMemorySize, SM1);
    cudaFuncSetAttribute((const void*)layer_kernel<128, 16, 1024, false>,
                         cudaFuncAttributeMaxDynamicSharedMemorySize, SM2);

    invdist_kernel<<<(NNODES * KNBR + 255) / 256, 256>>>(pos, nbr);
    wprep_kernel<<<(128 * 128 + 255) / 256, 256>>>(W0, 128, 128, wt0h, wt0l);
    wprep_kernel<<<(1024 * 128 + 255) / 256, 256>>>(W1, 1024, 128, wt1h, wt1l);
    wprep_kernel<<<(1024 * 16 + 255) / 256, 256>>>(W2, 1024, 16, wt2h, wt2l);

    layer_kernel<16, 128, 128, false>
        <<<NNODES / 128, 256, SM0>>>(h, nbr, wt0h, wt0l, b0, h1);
    layer_kernel<128, 128, 1024, true>
        <<<NNODES / 128, 256, SM1>>>(h1, nbr, wt1h, wt1l, b1, h2);
    layer_kernel<128, 16, 1024, false>
        <<<NNODES / 128, 256, SM2>>>(h2, nbr, wt2h, wt2l, b2, out);
}

// round 4
// speedup vs baseline: 3.8159x; 1.3151x over previous
#include <cuda_runtime.h>
#include <cuda_fp16.h>
#include <cstdint>
#include <math.h>

#define NNODES 262144
#define KNBR 8

// ---------------- global scratch (allocation-free) ----------------
__device__ float g_h1[(size_t)NNODES * 128];
__device__ float g_h2[(size_t)NNODES * 128];
__device__ float g_invd[(size_t)NNODES * KNBR];
// W transposed to [N, K] K-major, fp16 hi/lo
__device__ __half g_wt0h[128 * 128],  g_wt0l[128 * 128];
__device__ __half g_wt1h[128 * 1024], g_wt1l[128 * 1024];
__device__ __half g_wt2h[16 * 1024],  g_wt2l[16 * 1024];

// ---------------- helpers ----------------
__device__ __forceinline__ uint32_t smem_u32(const void* p) {
    uint32_t a;
    asm("{ .reg .u64 t; cvta.to.shared.u64 t, %1; cvt.u32.u64 %0, t; }"
        : "=r"(a) : "l"(p));
    return a;
}
__device__ __forceinline__ uint32_t swz128(uint32_t off) {
    return off ^ ((off >> 3) & 0x70);
}
__device__ __forceinline__ void ldsm4(uint32_t* r, uint32_t addr) {
    asm volatile("ldmatrix.sync.aligned.m8n8.x4.shared.b16 {%0,%1,%2,%3}, [%4];"
                 : "=r"(r[0]), "=r"(r[1]), "=r"(r[2]), "=r"(r[3]) : "r"(addr));
}
__device__ __forceinline__ void mma16816(float* d, const uint32_t* a,
                                         uint32_t b0, uint32_t b1) {
    asm volatile(
        "mma.sync.aligned.m16n8k16.row.col.f32.f16.f16.f32 "
        "{%0,%1,%2,%3}, {%4,%5,%6,%7}, {%8,%9}, {%0,%1,%2,%3};"
        : "+f"(d[0]), "+f"(d[1]), "+f"(d[2]), "+f"(d[3])
        : "r"(a[0]), "r"(a[1]), "r"(a[2]), "r"(a[3]), "r"(b0), "r"(b1));
}
// pack: lo half <- a, hi half <- b (cvt first src -> upper)
__device__ __forceinline__ uint32_t pack_h2(float a, float b) {
    uint32_t d;
    asm("cvt.rn.f16x2.f32 %0, %1, %2;" : "=r"(d) : "f"(b), "f"(a));
    return d;
}
__device__ __forceinline__ void cp_async16(uint32_t dst, const void* src) {
    asm volatile("cp.async.cg.shared.global [%0], [%1], 16;"
                 :: "r"(dst), "l"(src));
}
__device__ __forceinline__ void cp_commit_wait() {
    asm volatile("cp.async.commit_group;");
    asm volatile("cp.async.wait_group 0;");
}

// ---------------- small prep kernels ----------------
__global__ void invdist_kernel(const float* __restrict__ pos,
                               const int* __restrict__ nbr) {
    int i = blockIdx.x * blockDim.x + threadIdx.x;
    if (i >= NNODES * KNBR) return;
    int n = i >> 3;
    int j = nbr[i];
    float dx = pos[3 * n + 0] - pos[3 * j + 0];
    float dy = pos[3 * n + 1] - pos[3 * j + 1];
    float dz = pos[3 * n + 2] - pos[3 * j + 2];
    float d = sqrtf(dx * dx + dy * dy + dz * dz);
    g_invd[i] = (d == 0.0f) ? 2.0f : 1.0f / d;
}

// W [K, N] fp32 -> Wt [N, K] fp16 hi/lo
__global__ void wprep_kernel(const float* __restrict__ W, int K, int N,
                             __half* __restrict__ wh, __half* __restrict__ wl) {
    int i = blockIdx.x * blockDim.x + threadIdx.x;
    if (i >= K * N) return;
    int k = i / N, n = i % N;
    float w = W[i];
    __half h = __float2half_rn(w);
    float lo = w - __half2float(h);
    wh[n * K + k] = h;
    wl[n * K + k] = __float2half_rn(lo);
}

// ---------------- gathered GEMM layer via mma.sync fp16 -------------------
// NPASS==2: acc += Ah*Bh + Al*Bh   (err ~ W fp16 rounding ~2^-11)
// NPASS==3: acc += Ah*Bh + Al*Bh + Ah*Bl  (err ~2^-22)
template <int FIN, int FOUT, int KTOT, bool RELU, int NPASS>
struct Cfg {
    static constexpr int TM = 128;
    static constexpr int KC = 64;                 // 128B fp16 rows
    static constexpr int NCH = KTOT / KC;
    static constexpr int OFF_SN = 0;              // int  [128*8]
    static constexpr int OFF_SD = 4096;           // f32  [128*8]
    static constexpr int OFF_AH = 8192;           // fp16 [128][64] swizzled
    static constexpr int OFF_AL = OFF_AH + 128 * 128;
    static constexpr int OFF_BH = OFF_AL + 128 * 128;  // fp16 [FOUT][64]
    static constexpr int OFF_BL = OFF_BH + FOUT * 128;
    static constexpr int SMEM_BYTES = OFF_BL + ((NPASS == 3) ? FOUT * 128 : 0);
};

template <int FIN, int FOUT, int KTOT, bool RELU, int NPASS>
__global__ void __launch_bounds__(256, 2)
layer_kernel(const float* __restrict__ hin, const int* __restrict__ nbr,
             const __half* __restrict__ wh, const __half* __restrict__ wl,
             const float* __restrict__ bg, float* __restrict__ out) {
    using C = Cfg<FIN, FOUT, KTOT, RELU, NPASS>;
    extern __shared__ char smem[];
    const uint32_t sbase = smem_u32(smem);
    const int tid = threadIdx.x;
    const int wid = tid >> 5;
    const int lane = tid & 31;
    const int n0 = blockIdx.x * C::TM;

    int* sN = (int*)(smem + C::OFF_SN);
    float* sD = (float*)(smem + C::OFF_SD);
    for (int idx = tid; idx < C::TM * KNBR; idx += 256) {
        sN[idx] = nbr[n0 * KNBR + idx];
        sD[idx] = g_invd[(size_t)n0 * KNBR + idx];
    }

    float acc[FOUT / 8][4];
#pragma unroll
    for (int t = 0; t < FOUT / 8; t++) {
        acc[t][0] = 0.f; acc[t][1] = 0.f; acc[t][2] = 0.f; acc[t][3] = 0.f;
    }
    __syncthreads();

    const int mat = lane >> 3, r = lane & 7;
    const int mrow = wid * 16;

    for (int ch = 0; ch < C::NCH; ch++) {
        // ---- W tile staging via cp.async (overlaps the gather below) ----
        for (int idx = tid; idx < FOUT * 8; idx += 256) {
            int row = idx >> 3, c = idx & 7;
            uint32_t off = swz128((uint32_t)(row * 128 + c * 16));
            const __half* src = wh + (size_t)row * KTOT + ch * C::KC + c * 8;
            cp_async16(sbase + C::OFF_BH + off, src);
            if (NPASS == 3) {
                const __half* srcl = wl + (size_t)row * KTOT + ch * C::KC + c * 8;
                cp_async16(sbase + C::OFF_BL + off, srcl);
            }
        }
        asm volatile("cp.async.commit_group;");

        // ---- gather + scale + fp16 hi/lo split of A tile [128, 64] ----
        for (int idx = tid; idx < C::TM * 16; idx += 256) {
            int row = idx >> 4, q = idx & 15;
            int j = ch * C::KC + q * 4;
            int k = j / FIN, f = j % FIN;
            const float4 v = *reinterpret_cast<const float4*>(
                hin + (size_t)sN[row * KNBR + k] * FIN + f);
            float s = sD[row * KNBR + k];
            float x0 = v.x * s, x1 = v.y * s, x2 = v.z * s, x3 = v.w * s;
            uint32_t ph0 = pack_h2(x0, x1);
            uint32_t ph1 = pack_h2(x2, x3);
            float2 f0 = __half22float2(*reinterpret_cast<__half2*>(&ph0));
            float2 f1 = __half22float2(*reinterpret_cast<__half2*>(&ph1));
            uint32_t pl0 = pack_h2(x0 - f0.x, x1 - f0.y);
            uint32_t pl1 = pack_h2(x2 - f1.x, x3 - f1.y);
            uint32_t off = swz128((uint32_t)(row * 128 + q * 8));
            *reinterpret_cast<uint2*>(smem + C::OFF_AH + off) = make_uint2(ph0, ph1);
            *reinterpret_cast<uint2*>(smem + C::OFF_AL + off) = make_uint2(pl0, pl1);
        }
        asm volatile("cp.async.wait_group 0;");
        __syncthreads();

#pragma unroll
        for (int ks = 0; ks < C::KC / 16; ks++) {
            int arow = mrow + ((mat & 1) << 3) + r;
            int acol = (ks << 4) + ((mat >> 1) << 3);
            uint32_t abyte = swz128((uint32_t)(arow * 128 + acol * 2));
            uint32_t ah[4], al[4];
            ldsm4(ah, sbase + C::OFF_AH + abyte);
            ldsm4(al, sbase + C::OFF_AL + abyte);
#pragma unroll
            for (int nt2 = 0; nt2 < FOUT / 16; nt2++) {
                int brow = nt2 * 16 + ((mat >> 1) << 3) + r;
                int bcol = (ks << 4) + ((mat & 1) << 3);
                uint32_t bbyte = swz128((uint32_t)(brow * 128 + bcol * 2));
                uint32_t bh[4];
                ldsm4(bh, sbase + C::OFF_BH + bbyte);
                float* d0 = acc[nt2 * 2];
                float* d1 = acc[nt2 * 2 + 1];
                mma16816(d0, ah, bh[0], bh[1]);
                mma16816(d0, al, bh[0], bh[1]);
                mma16816(d1, ah, bh[2], bh[3]);
                mma16816(d1, al, bh[2], bh[3]);
                if (NPASS == 3) {
                    uint32_t bl[4];
                    ldsm4(bl, sbase + C::OFF_BL + bbyte);
                    mma16816(d0, ah, bl[0], bl[1]);
                    mma16816(d1, ah, bl[2], bl[3]);
                }
            }
        }
        __syncthreads();
    }

    // ---- epilogue: bias (+LeakyReLU), float2 stores ----
    const int g = lane >> 2, tig = lane & 3;
    const int row0 = n0 + mrow + g;
#pragma unroll
    for (int nt = 0; nt < FOUT / 8; nt++) {
        int col = nt * 8 + tig * 2;
        float b0 = bg[col], b1 = bg[col + 1];
        float v00 = acc[nt][0] + b0, v01 = acc[nt][1] + b1;
        float v10 = acc[nt][2] + b0, v11 = acc[nt][3] + b1;
        if (RELU) {
            v00 = (v00 >= 0.f) ? v00 : 0.01f * v00;
            v01 = (v01 >= 0.f) ? v01 : 0.01f * v01;
            v10 = (v10 >= 0.f) ? v10 : 0.01f * v10;
            v11 = (v11 >= 0.f) ? v11 : 0.01f * v11;
        }
        *reinterpret_cast<float2*>(out + (size_t)row0 * FOUT + col) =
            make_float2(v00, v01);
        *reinterpret_cast<float2*>(out + (size_t)(row0 + 8) * FOUT + col) =
            make_float2(v10, v11);
    }
}

// ---------------- host launch ----------------
extern "C" void kernel_launch(void* const* d_in, const int* in_sizes, int n_in,
                              void* d_out, int out_size) {
    const float* h   = (const float*)d_in[0];
    const float* pos = (const float*)d_in[1];
    const int*   nbr = (const int*)d_in[2];
    const float* W0  = (const float*)d_in[3];
    const float* b0  = (const float*)d_in[4];
    const float* W1  = (const float*)d_in[5];
    const float* b1  = (const float*)d_in[6];
    const float* W2  = (const float*)d_in[7];
    const float* b2  = (const float*)d_in[8];
    float* out = (float*)d_out;

    float *h1, *h2;
    cudaGetSymbolAddress((void**)&h1, g_h1);
    cudaGetSymbolAddress((void**)&h2, g_h2);
    __half *wt0h, *wt0l, *wt1h, *wt1l, *wt2h, *wt2l;
    cudaGetSymbolAddress((void**)&wt0h, g_wt0h);
    cudaGetSymbolAddress((void**)&wt0l, g_wt0l);
    cudaGetSymbolAddress((void**)&wt1h, g_wt1h);
    cudaGetSymbolAddress((void**)&wt1l, g_wt1l);
    cudaGetSymbolAddress((void**)&wt2h, g_wt2h);
    cudaGetSymbolAddress((void**)&wt2l, g_wt2l);

    constexpr int SM0 = Cfg<16, 128, 128, false, 3>::SMEM_BYTES;
    constexpr int SM1 = Cfg<128, 128, 1024, true, 2>::SMEM_BYTES;
    constexpr int SM2 = Cfg<128, 16, 1024, false, 3>::SMEM_BYTES;

    cudaFuncSetAttribute((const void*)layer_kernel<16, 128, 128, false, 3>,
                         cudaFuncAttributeMaxDynamicSharedMemorySize, SM0);
    cudaFuncSetAttribute((const void*)layer_kernel<128, 128, 1024, true, 2>,
                         cudaFuncAttributeMaxDynamicSharedMemorySize, SM1);
    cudaFuncSetAttribute((const void*)layer_kernel<128, 16, 1024, false, 3>,
                         cudaFuncAttributeMaxDynamicSharedMemorySize, SM2);

    invdist_kernel<<<(NNODES * KNBR + 255) / 256, 256>>>(pos, nbr);
    wprep_kernel<<<(128 * 128 + 255) / 256, 256>>>(W0, 128, 128, wt0h, wt0l);
    wprep_kernel<<<(1024 * 128 + 255) / 256, 256>>>(W1, 1024, 128, wt1h, wt1l);
    wprep_kernel<<<(1024 * 16 + 255) / 256, 256>>>(W2, 1024, 16, wt2h, wt2l);

    layer_kernel<16, 128, 128, false, 3>
        <<<NNODES / 128, 256, SM0>>>(h, nbr, wt0h, wt0l, b0, h1);
    layer_kernel<128, 128, 1024, true, 2>
        <<<NNODES / 128, 256, SM1>>>(h1, nbr, wt1h, wt1l, b1, h2);
    layer_kernel<128, 16, 1024, false, 3>
        <<<NNODES / 128, 256, SM2>>>(h2, nbr, wt2h, wt2l, b2, out);
}

// round 5
// speedup vs baseline: 6.6504x; 1.7428x over previous
#include <cuda_runtime.h>
#include <cuda_fp16.h>
#include <cstdint>
#include <math.h>

#define NNODES 262144
#define KNBR 8

// ---------------- global scratch (allocation-free) ----------------
__device__ float g_h1[(size_t)NNODES * 128];
__device__ float g_h2[(size_t)NNODES * 128];
__device__ float g_invd[(size_t)NNODES * KNBR];
// W transposed to [N, K] K-major, fp16 hi/lo
__device__ __half g_wt0h[128 * 128],  g_wt0l[128 * 128];
__device__ __half g_wt1h[128 * 1024], g_wt1l[128 * 1024];
__device__ __half g_wt2h[16 * 1024],  g_wt2l[16 * 1024];

// ---------------- helpers ----------------
__device__ __forceinline__ uint32_t smem_u32(const void* p) {
    uint32_t a;
    asm("{ .reg .u64 t; cvta.to.shared.u64 t, %1; cvt.u32.u64 %0, t; }"
        : "=r"(a) : "l"(p));
    return a;
}
__device__ __forceinline__ uint32_t swz128(uint32_t off) {
    return off ^ ((off >> 3) & 0x70);
}
__device__ __forceinline__ void ldsm4(uint32_t* r, uint32_t addr) {
    asm volatile("ldmatrix.sync.aligned.m8n8.x4.shared.b16 {%0,%1,%2,%3}, [%4];"
                 : "=r"(r[0]), "=r"(r[1]), "=r"(r[2]), "=r"(r[3]) : "r"(addr));
}
__device__ __forceinline__ void mma16816(float* d, const uint32_t* a,
                                         uint32_t b0, uint32_t b1) {
    asm volatile(
        "mma.sync.aligned.m16n8k16.row.col.f32.f16.f16.f32 "
        "{%0,%1,%2,%3}, {%4,%5,%6,%7}, {%8,%9}, {%0,%1,%2,%3};"
        : "+f"(d[0]), "+f"(d[1]), "+f"(d[2]), "+f"(d[3])
        : "r"(a[0]), "r"(a[1]), "r"(a[2]), "r"(a[3]), "r"(b0), "r"(b1));
}
__device__ __forceinline__ uint32_t pack_h2(float a, float b) {
    uint32_t d;
    asm("cvt.rn.f16x2.f32 %0, %1, %2;" : "=r"(d) : "f"(b), "f"(a));
    return d;
}
__device__ __forceinline__ void cp_async16(uint32_t dst, const void* src) {
    asm volatile("cp.async.cg.shared.global [%0], [%1], 16;"
                 :: "r"(dst), "l"(src));
}

// ---------------- small prep kernels ----------------
__global__ void invdist_kernel(const float* __restrict__ pos,
                               const int* __restrict__ nbr) {
    int i = blockIdx.x * blockDim.x + threadIdx.x;
    if (i >= NNODES * KNBR) return;
    int n = i >> 3;
    int j = nbr[i];
    float dx = pos[3 * n + 0] - pos[3 * j + 0];
    float dy = pos[3 * n + 1] - pos[3 * j + 1];
    float dz = pos[3 * n + 2] - pos[3 * j + 2];
    float d = sqrtf(dx * dx + dy * dy + dz * dz);
    g_invd[i] = (d == 0.0f) ? 2.0f : 1.0f / d;
}

__global__ void wprep_kernel(const float* __restrict__ W, int K, int N,
                             __half* __restrict__ wh, __half* __restrict__ wl) {
    int i = blockIdx.x * blockDim.x + threadIdx.x;
    if (i >= K * N) return;
    int k = i / N, n = i % N;
    float w = W[i];
    __half h = __float2half_rn(w);
    float lo = w - __half2float(h);
    wh[n * K + k] = h;
    wl[n * K + k] = __float2half_rn(lo);
}

// ============ pipelined gathered-GEMM (layers 1 & 2) ============
// NPASS==1: acc += Ah*Bh              (err ~ fp16 rounding of A and W)
// NPASS==3: acc += Ah*Bh + Al*Bh + Ah*Bl
template <int FIN, int FOUT, int KTOT, bool RELU, int NPASS>
struct PCfg {
    static constexpr int TM = 128;
    static constexpr int KC = 64;
    static constexpr int NCH = KTOT / KC;
    static constexpr int APARTS = (NPASS == 3) ? 2 : 1;
    static constexpr int BPARTS = (NPASS == 3) ? 2 : 1;
    static constexpr int ABUF = 128 * 128;       // bytes per A part
    static constexpr int BBUF = FOUT * 128;      // bytes per B part
    static constexpr int STRIDE = APARTS * ABUF + BPARTS * BBUF;
    static constexpr int OFF_SN = 0;
    static constexpr int OFF_SD = 4096;
    static constexpr int BASE = 8192;
    static __device__ __forceinline__ int offA(int b)  { return BASE + b * STRIDE; }
    static __device__ __forceinline__ int offAL(int b) { return BASE + b * STRIDE + ABUF; }
    static __device__ __forceinline__ int offB(int b)  { return BASE + b * STRIDE + APARTS * ABUF; }
    static __device__ __forceinline__ int offBL(int b) { return BASE + b * STRIDE + APARTS * ABUF + BBUF; }
    static constexpr int SMEM_BYTES = BASE + 2 * STRIDE;
};

template <int FIN, int FOUT, int KTOT, bool RELU, int NPASS>
__global__ void __launch_bounds__(256, 2)
layer_pipe_kernel(const float* __restrict__ hin, const int* __restrict__ nbr,
                  const __half* __restrict__ wh, const __half* __restrict__ wl,
                  const float* __restrict__ bg, float* __restrict__ out) {
    using C = PCfg<FIN, FOUT, KTOT, RELU, NPASS>;
    extern __shared__ char smem[];
    const uint32_t sbase = smem_u32(smem);
    const int tid = threadIdx.x;
    const int wid = tid >> 5;
    const int lane = tid & 31;
    const int n0 = blockIdx.x * C::TM;

    int* sN = (int*)(smem + C::OFF_SN);
    float* sD = (float*)(smem + C::OFF_SD);
    for (int idx = tid; idx < C::TM * KNBR; idx += 256) {
        sN[idx] = nbr[n0 * KNBR + idx];
        sD[idx] = g_invd[(size_t)n0 * KNBR + idx];
    }

    float acc[FOUT / 8][4];
#pragma unroll
    for (int t = 0; t < FOUT / 8; t++) {
        acc[t][0] = 0.f; acc[t][1] = 0.f; acc[t][2] = 0.f; acc[t][3] = 0.f;
    }
    __syncthreads();

    // ---- stage B chunk helper (cp.async) ----
    auto stageB = [&](int ch, int buf) {
#pragma unroll 2
        for (int idx = tid; idx < FOUT * 8; idx += 256) {
            int row = idx >> 3, c = idx & 7;
            uint32_t off = swz128((uint32_t)(row * 128 + c * 16));
            cp_async16(sbase + C::offB(buf) + off,
                       wh + (size_t)row * KTOT + ch * C::KC + c * 8);
            if (NPASS == 3)
                cp_async16(sbase + C::offBL(buf) + off,
                           wl + (size_t)row * KTOT + ch * C::KC + c * 8);
        }
        asm volatile("cp.async.commit_group;");
    };
    // ---- convert+store one A element group ----
    auto convA = [&](int buf, int idx, float4 v, float s) {
        int row = idx >> 4, q = idx & 15;
        float x0 = v.x * s, x1 = v.y * s, x2 = v.z * s, x3 = v.w * s;
        uint32_t ph0 = pack_h2(x0, x1);
        uint32_t ph1 = pack_h2(x2, x3);
        uint32_t off = swz128((uint32_t)(row * 128 + q * 8));
        *reinterpret_cast<uint2*>(smem + C::offA(buf) + off) = make_uint2(ph0, ph1);
        if (NPASS == 3) {
            float2 f0 = __half22float2(*reinterpret_cast<__half2*>(&ph0));
            float2 f1 = __half22float2(*reinterpret_cast<__half2*>(&ph1));
            uint32_t pl0 = pack_h2(x0 - f0.x, x1 - f0.y);
            uint32_t pl1 = pack_h2(x2 - f1.x, x3 - f1.y);
            *reinterpret_cast<uint2*>(smem + C::offAL(buf) + off) = make_uint2(pl0, pl1);
        }
    };

    // ---- prologue: chunk 0 ----
    stageB(0, 0);
#pragma unroll
    for (int t = 0; t < 8; t++) {
        int idx = tid + t * 256;
        int row = idx >> 4, q = idx & 15;
        int j = q * 4;
        int k = j / FIN, f = j % FIN;
        float4 v = *reinterpret_cast<const float4*>(
            hin + (size_t)sN[row * KNBR + k] * FIN + f);
        convA(0, idx, v, sD[row * KNBR + k]);
    }
    asm volatile("cp.async.wait_group 0;");
    __syncthreads();

    const int mat = lane >> 3, r = lane & 7;
    const int mrow = wid * 16;

    float4 av[8];
    for (int ch = 0; ch < C::NCH; ch++) {
        const int cur = ch & 1;
        const bool more = (ch + 1 < C::NCH);
        if (more) {
            stageB(ch + 1, cur ^ 1);
#pragma unroll
            for (int t = 0; t < 8; t++) {
                int idx = tid + t * 256;
                int row = idx >> 4, q = idx & 15;
                int j = (ch + 1) * C::KC + q * 4;
                int k = j / FIN, f = j % FIN;
                av[t] = *reinterpret_cast<const float4*>(
                    hin + (size_t)sN[row * KNBR + k] * FIN + f);
            }
        }

        // ---- MMA on current buffers ----
#pragma unroll
        for (int ks = 0; ks < C::KC / 16; ks++) {
            int arow = mrow + ((mat & 1) << 3) + r;
            int acol = (ks << 4) + ((mat >> 1) << 3);
            uint32_t abyte = swz128((uint32_t)(arow * 128 + acol * 2));
            uint32_t ah[4], al[4];
            ldsm4(ah, sbase + C::offA(cur) + abyte);
            if (NPASS == 3) ldsm4(al, sbase + C::offAL(cur) + abyte);
#pragma unroll
            for (int nt2 = 0; nt2 < FOUT / 16; nt2++) {
                int brow = nt2 * 16 + ((mat >> 1) << 3) + r;
                int bcol = (ks << 4) + ((mat & 1) << 3);
                uint32_t bbyte = swz128((uint32_t)(brow * 128 + bcol * 2));
                uint32_t bh[4];
                ldsm4(bh, sbase + C::offB(cur) + bbyte);
                float* d0 = acc[nt2 * 2];
                float* d1 = acc[nt2 * 2 + 1];
                mma16816(d0, ah, bh[0], bh[1]);
                mma16816(d1, ah, bh[2], bh[3]);
                if (NPASS == 3) {
                    uint32_t bl[4];
                    ldsm4(bl, sbase + C::offBL(cur) + bbyte);
                    mma16816(d0, al, bh[0], bh[1]);
                    mma16816(d1, al, bh[2], bh[3]);
                    mma16816(d0, ah, bl[0], bl[1]);
                    mma16816(d1, ah, bl[2], bl[3]);
                }
            }
        }

        if (more) {
#pragma unroll
            for (int t = 0; t < 8; t++) {
                int idx = tid + t * 256;
                int row = idx >> 4, q = idx & 15;
                int j = (ch + 1) * C::KC + q * 4;
                int k = j / FIN;
                convA(cur ^ 1, idx, av[t], sD[row * KNBR + k]);
            }
            asm volatile("cp.async.wait_group 0;");
        }
        __syncthreads();
    }

    // ---- epilogue ----
    const int g = lane >> 2, tig = lane & 3;
    const int row0 = n0 + mrow + g;
#pragma unroll
    for (int nt = 0; nt < FOUT / 8; nt++) {
        int col = nt * 8 + tig * 2;
        float b0 = bg[col], b1 = bg[col + 1];
        float v00 = acc[nt][0] + b0, v01 = acc[nt][1] + b1;
        float v10 = acc[nt][2] + b0, v11 = acc[nt][3] + b1;
        if (RELU) {
            v00 = (v00 >= 0.f) ? v00 : 0.01f * v00;
            v01 = (v01 >= 0.f) ? v01 : 0.01f * v01;
            v10 = (v10 >= 0.f) ? v10 : 0.01f * v10;
            v11 = (v11 >= 0.f) ? v11 : 0.01f * v11;
        }
        *reinterpret_cast<float2*>(out + (size_t)row0 * FOUT + col) =
            make_float2(v00, v01);
        *reinterpret_cast<float2*>(out + (size_t)(row0 + 8) * FOUT + col) =
            make_float2(v10, v11);
    }
}

// ============ simple kernel for layer 0 (small, 3-pass) ============
__global__ void __launch_bounds__(256, 2)
layer0_kernel(const float* __restrict__ hin, const int* __restrict__ nbr,
              const __half* __restrict__ wh, const __half* __restrict__ wl,
              const float* __restrict__ bg, float* __restrict__ out) {
    constexpr int FIN = 16, FOUT = 128, KTOT = 128, KC = 64, NCH = 2;
    constexpr int OFF_SN = 0, OFF_SD = 4096, OFF_AH = 8192;
    constexpr int OFF_AL = OFF_AH + 128 * 128;
    constexpr int OFF_BH = OFF_AL + 128 * 128;
    constexpr int OFF_BL = OFF_BH + FOUT * 128;
    extern __shared__ char smem[];
    const uint32_t sbase = smem_u32(smem);
    const int tid = threadIdx.x, wid = tid >> 5, lane = tid & 31;
    const int n0 = blockIdx.x * 128;

    int* sN = (int*)(smem + OFF_SN);
    float* sD = (float*)(smem + OFF_SD);
    for (int idx = tid; idx < 128 * KNBR; idx += 256) {
        sN[idx] = nbr[n0 * KNBR + idx];
        sD[idx] = g_invd[(size_t)n0 * KNBR + idx];
    }
    float acc[FOUT / 8][4];
#pragma unroll
    for (int t = 0; t < FOUT / 8; t++) {
        acc[t][0] = 0.f; acc[t][1] = 0.f; acc[t][2] = 0.f; acc[t][3] = 0.f;
    }
    __syncthreads();
    const int mat = lane >> 3, r = lane & 7;
    const int mrow = wid * 16;

    for (int ch = 0; ch < NCH; ch++) {
        for (int idx = tid; idx < FOUT * 8; idx += 256) {
            int row = idx >> 3, c = idx & 7;
            uint32_t off = swz128((uint32_t)(row * 128 + c * 16));
            cp_async16(sbase + OFF_BH + off, wh + (size_t)row * KTOT + ch * KC + c * 8);
            cp_async16(sbase + OFF_BL + off, wl + (size_t)row * KTOT + ch * KC + c * 8);
        }
        asm volatile("cp.async.commit_group;");
        for (int idx = tid; idx < 128 * 16; idx += 256) {
            int row = idx >> 4, q = idx & 15;
            int j = ch * KC + q * 4;
            int k = j / FIN, f = j % FIN;
            const float4 v = *reinterpret_cast<const float4*>(
                hin + (size_t)sN[row * KNBR + k] * FIN + f);
            float s = sD[row * KNBR + k];
            float x0 = v.x * s, x1 = v.y * s, x2 = v.z * s, x3 = v.w * s;
            uint32_t ph0 = pack_h2(x0, x1), ph1 = pack_h2(x2, x3);
            float2 f0 = __half22float2(*reinterpret_cast<__half2*>(&ph0));
            float2 f1 = __half22float2(*reinterpret_cast<__half2*>(&ph1));
            uint32_t pl0 = pack_h2(x0 - f0.x, x1 - f0.y);
            uint32_t pl1 = pack_h2(x2 - f1.x, x3 - f1.y);
            uint32_t off = swz128((uint32_t)(row * 128 + q * 8));
            *reinterpret_cast<uint2*>(smem + OFF_AH + off) = make_uint2(ph0, ph1);
            *reinterpret_cast<uint2*>(smem + OFF_AL + off) = make_uint2(pl0, pl1);
        }
        asm volatile("cp.async.wait_group 0;");
        __syncthreads();
#pragma unroll
        for (int ks = 0; ks < KC / 16; ks++) {
            int arow = mrow + ((mat & 1) << 3) + r;
            int acol = (ks << 4) + ((mat >> 1) << 3);
            uint32_t abyte = swz128((uint32_t)(arow * 128 + acol * 2));
            uint32_t ah[4], al[4];
            ldsm4(ah, sbase + OFF_AH + abyte);
            ldsm4(al, sbase + OFF_AL + abyte);
#pragma unroll
            for (int nt2 = 0; nt2 < FOUT / 16; nt2++) {
                int brow = nt2 * 16 + ((mat >> 1) << 3) + r;
                int bcol = (ks << 4) + ((mat & 1) << 3);
                uint32_t bbyte = swz128((uint32_t)(brow * 128 + bcol * 2));
                uint32_t bh[4], bl[4];
                ldsm4(bh, sbase + OFF_BH + bbyte);
                ldsm4(bl, sbase + OFF_BL + bbyte);
                float* d0 = acc[nt2 * 2];
                float* d1 = acc[nt2 * 2 + 1];
                mma16816(d0, ah, bh[0], bh[1]);
                mma16816(d0, al, bh[0], bh[1]);
                mma16816(d0, ah, bl[0], bl[1]);
                mma16816(d1, ah, bh[2], bh[3]);
                mma16816(d1, al, bh[2], bh[3]);
                mma16816(d1, ah, bl[2], bl[3]);
            }
        }
        __syncthreads();
    }
    const int g = lane >> 2, tig = lane & 3;
    const int row0 = n0 + mrow + g;
#pragma unroll
    for (int nt = 0; nt < FOUT / 8; nt++) {
        int col = nt * 8 + tig * 2;
        float b0 = bg[col], b1 = bg[col + 1];
        *reinterpret_cast<float2*>(out + (size_t)row0 * FOUT + col) =
            make_float2(acc[nt][0] + b0, acc[nt][1] + b1);
        *reinterpret_cast<float2*>(out + (size_t)(row0 + 8) * FOUT + col) =
            make_float2(acc[nt][2] + b0, acc[nt][3] + b1);
    }
}

// ---------------- host launch ----------------
extern "C" void kernel_launch(void* const* d_in, const int* in_sizes, int n_in,
                              void* d_out, int out_size) {
    const float* h   = (const float*)d_in[0];
    const float* pos = (const float*)d_in[1];
    const int*   nbr = (const int*)d_in[2];
    const float* W0  = (const float*)d_in[3];
    const float* b0  = (const float*)d_in[4];
    const float* W1  = (const float*)d_in[5];
    const float* b1  = (const float*)d_in[6];
    const float* W2  = (const float*)d_in[7];
    const float* b2  = (const float*)d_in[8];
    float* out = (float*)d_out;

    float *h1, *h2;
    cudaGetSymbolAddress((void**)&h1, g_h1);
    cudaGetSymbolAddress((void**)&h2, g_h2);
    __half *wt0h, *wt0l, *wt1h, *wt1l, *wt2h, *wt2l;
    cudaGetSymbolAddress((void**)&wt0h, g_wt0h);
    cudaGetSymbolAddress((void**)&wt0l, g_wt0l);
    cudaGetSymbolAddress((void**)&wt1h, g_wt1h);
    cudaGetSymbolAddress((void**)&wt1l, g_wt1l);
    cudaGetSymbolAddress((void**)&wt2h, g_wt2h);
    cudaGetSymbolAddress((void**)&wt2l, g_wt2l);

    constexpr int SM0 = 8192 + 2 * 128 * 128 + 2 * 128 * 128;      // layer0 simple
    constexpr int SM1 = PCfg<128, 128, 1024, true, 1>::SMEM_BYTES;  // 73728
    constexpr int SM2 = PCfg<128, 16, 1024, false, 3>::SMEM_BYTES;  // 81920

    cudaFuncSetAttribute((const void*)layer0_kernel,
                         cudaFuncAttributeMaxDynamicSharedMemorySize, SM0);
    cudaFuncSetAttribute((const void*)layer_pipe_kernel<128, 128, 1024, true, 1>,
                         cudaFuncAttributeMaxDynamicSharedMemorySize, SM1);
    cudaFuncSetAttribute((const void*)layer_pipe_kernel<128, 16, 1024, false, 3>,
                         cudaFuncAttributeMaxDynamicSharedMemorySize, SM2);

    invdist_kernel<<<(NNODES * KNBR + 255) / 256, 256>>>(pos, nbr);
    wprep_kernel<<<(128 * 128 + 255) / 256, 256>>>(W0, 128, 128, wt0h, wt0l);
    wprep_kernel<<<(1024 * 128 + 255) / 256, 256>>>(W1, 1024, 128, wt1h, wt1l);
    wprep_kernel<<<(1024 * 16 + 255) / 256, 256>>>(W2, 1024, 16, wt2h, wt2l);

    layer0_kernel<<<NNODES / 128, 256, SM0>>>(h, nbr, wt0h, wt0l, b0, h1);
    layer_pipe_kernel<128, 128, 1024, true, 1>
        <<<NNODES / 128, 256, SM1>>>(h1, nbr, wt1h, wt1l, b1, h2);
    layer_pipe_kernel<128, 16, 1024, false, 3>
        <<<NNODES / 128, 256, SM2>>>(h2, nbr, wt2h, wt2l, b2, out);
}